// round 14
// baseline (speedup 1.0000x reference)
#include <cuda_runtime.h>
#include <cuda_fp16.h>
#include <math.h>
#include <stdint.h>

// Problem constants
#define NB 4
#define LL 2048
#define CC 512
#define DIN 1024
#define DS 16
#define DCONV 4
#define DTR 32
#define NT (NB * LL)   // 8192 rows
#define EPSBN 1e-5f
#define NCH 4
#define CHL (LL / NCH)  // 512

// ---------------- scratch (device globals; no allocation allowed) -------------
__device__ __align__(256) __half  g_x16 [NT * CC];
__device__ __align__(256) __half  g_hg16[NT * CC];
__device__ __align__(256) __half  g_xz16[NT * 2 * DIN];
__device__ __align__(256) __half  g_xc16[NT * DIN];
__device__ __align__(256) __half  g_db16[NT * 64];
__device__ __align__(256) __half  g_dt16[NT * DIN];
__device__ __align__(256) __half2 g_uz16[NT * DIN];   // {silu(u), silu(z)}
__device__ __align__(256) __half  g_y16 [NT * DIN];
__device__ __align__(256) __half  g_og16[NT * CC];
// chunked-scan state
__device__ __align__(256) float g_hend [3 * NB * DIN * DS];
__device__ __align__(256) float g_send [3 * NB * DIN];
__device__ __align__(256) float g_hinit[NCH * NB * DIN * DS];
// fp16 weights
__device__ __align__(256) __half g_Win_h[CC * CC];
__device__ __align__(256) __half g_ip_h [2 * DIN * CC];
__device__ __align__(256) __half g_xp_h [64 * DIN];
__device__ __align__(256) __half g_dtp_h[DIN * DTR];
__device__ __align__(256) __half g_op_h [CC * DIN];
__device__ __align__(256) __half g_Wo_h [CC * CC];

// ============================ PTX helpers =====================================
__device__ __forceinline__ uint32_t smem_u32(const void* p) {
    uint32_t a;
    asm("{ .reg .u64 t; cvta.to.shared.u64 t, %1; cvt.u32.u64 %0, t; }"
        : "=r"(a) : "l"(p));
    return a;
}
__device__ __forceinline__ void cpa16(uint32_t d, const void* s) {
    asm volatile("cp.async.cg.shared.global [%0], [%1], 16;" :: "r"(d), "l"(s));
}
#define CP_COMMIT asm volatile("cp.async.commit_group;" ::: "memory")
#define CP_WAIT1  asm volatile("cp.async.wait_group 1;"  ::: "memory")
#define CP_WAIT2  asm volatile("cp.async.wait_group 2;"  ::: "memory")

__device__ __forceinline__ void ldsm4(uint32_t* r, uint32_t a) {
    asm volatile("ldmatrix.sync.aligned.m8n8.x4.shared.b16 {%0,%1,%2,%3}, [%4];"
        : "=r"(r[0]), "=r"(r[1]), "=r"(r[2]), "=r"(r[3]) : "r"(a));
}
__device__ __forceinline__ void mma16816(float* c, const uint32_t* a, const uint32_t* b) {
    asm volatile(
        "mma.sync.aligned.m16n8k16.row.col.f32.f16.f16.f32 "
        "{%0,%1,%2,%3}, {%4,%5,%6,%7}, {%8,%9}, {%0,%1,%2,%3};"
        : "+f"(c[0]), "+f"(c[1]), "+f"(c[2]), "+f"(c[3])
        : "r"(a[0]), "r"(a[1]), "r"(a[2]), "r"(a[3]), "r"(b[0]), "r"(b[1]));
}

// ====================== single-term fp16 HMMA GEMM ============================
// (unchanged — known good)
template <int MT, int NTILE>
__device__ __forceinline__ void load_stage(
    uint32_t base, int tid, int m0, int n0, int lda, int K, int c,
    const __half* A, const __half* W)
{
    const int k0 = c * 32;
    #pragma unroll
    for (int e = 0; e < MT * 4 / 256; e++) {
        int t = tid + e * 256;
        int r = t >> 2, g = t & 3;
        cpa16(base + r * 80 + g * 16, A + (size_t)(m0 + r) * lda + k0 + g * 8);
    }
    uint32_t dw = base + (uint32_t)MT * 80;
    #pragma unroll
    for (int e = 0; e < NTILE * 4 / 256; e++) {
        int t = tid + e * 256;
        int r = t >> 2, g = t & 3;
        cpa16(dw + r * 80 + g * 16, W + (size_t)(n0 + r) * K + k0 + g * 8);
    }
}

template <int MT, int NTILE, int WMW, int WNW>
__global__ void __launch_bounds__(256, 2) gemm_fp16(
    const __half* __restrict__ A, int lda,
    const __half* __restrict__ W, int K,
    float* __restrict__ outF, __half* __restrict__ outH,
    const int* __restrict__ scat, int Ntot, int epi,
    const float* __restrict__ p0, const float* __restrict__ p1,
    const float* __restrict__ p2, const float* __restrict__ p3,
    const float* __restrict__ addsrc)
{
    constexpr int WTM = MT / WMW;
    constexpr int WTN = NTILE / WNW;
    constexpr int MTFR = WTM / 16;
    constexpr int NT8 = WTN / 8;
    constexpr int STAGE = (MT + NTILE) * 80;

    extern __shared__ __align__(128) char smraw[];
    const uint32_t sb = smem_u32(smraw);

    const int tid = threadIdx.x;
    const int lane = tid & 31, warp = tid >> 5;
    const int wm = warp % WMW, wn = warp / WMW;
    const int m0 = blockIdx.y * MT;
    const int n0 = blockIdx.x * NTILE;

    float acc[MTFR][NT8][4] = {};

    const int nch = K >> 5;
    #pragma unroll
    for (int s = 0; s < 3; s++) {
        if (s < nch)
            load_stage<MT, NTILE>(sb + s * STAGE, tid, m0, n0, lda, K, s, A, W);
        CP_COMMIT;
    }

    const int lr = lane & 15;
    const int lc = (lane >> 4) << 3;

    for (int c = 0; c < nch; c++) {
        CP_WAIT2;
        __syncthreads();
        {
            int cn = c + 3;
            if (cn < nch)
                load_stage<MT, NTILE>(sb + (cn & 3) * STAGE, tid, m0, n0, lda, K, cn, A, W);
            CP_COMMIT;
        }
        const uint32_t cur = sb + (uint32_t)(c & 3) * STAGE;
        #pragma unroll
        for (int kk = 0; kk < 32; kk += 16) {
            uint32_t af[MTFR][4];
            #pragma unroll
            for (int mt = 0; mt < MTFR; mt++)
                ldsm4(af[mt], cur + (uint32_t)((wm * WTM + mt * 16 + lr) * 80 + (kk + lc) * 2));
            uint32_t wf[NT8][2];
            #pragma unroll
            for (int p = 0; p < NT8 / 2; p++) {
                uint32_t a = cur + (uint32_t)((MT + wn * WTN + p * 16 + lr) * 80 + (kk + lc) * 2);
                uint32_t r4[4];
                ldsm4(r4, a);
                wf[2*p][0] = r4[0]; wf[2*p][1] = r4[2];
                wf[2*p+1][0] = r4[1]; wf[2*p+1][1] = r4[3];
            }
            #pragma unroll
            for (int mt = 0; mt < MTFR; mt++)
                #pragma unroll
                for (int nt = 0; nt < NT8; nt++)
                    mma16816(acc[mt][nt], af[mt], wf[nt]);
        }
    }

    const int g = lane >> 2, tg = lane & 3;
    #pragma unroll
    for (int mt = 0; mt < MTFR; mt++)
        #pragma unroll
        for (int nt = 0; nt < NT8; nt++)
            #pragma unroll
            for (int rr = 0; rr < 2; rr++) {
                int m = m0 + wm * WTM + mt * 16 + g + rr * 8;
                int n = n0 + wn * WTN + nt * 8 + tg * 2;
                int mo = scat ? scat[m] : m;
                float v0 = acc[mt][nt][rr * 2 + 0];
                float v1 = acc[mt][nt][rr * 2 + 1];
                if (epi == 1) {
                    v0 = fmaxf((v0 - p2[n])   * rsqrtf(p3[n]   + EPSBN) * p0[n]   + p1[n],   0.f);
                    v1 = fmaxf((v1 - p2[n+1]) * rsqrtf(p3[n+1] + EPSBN) * p0[n+1] + p1[n+1], 0.f);
                } else if (epi == 2) {
                    v0 += p0[n];   v0 = (v0 > 20.f) ? v0 : __logf(1.f + __expf(v0));
                    v1 += p0[n+1]; v1 = (v1 > 20.f) ? v1 : __logf(1.f + __expf(v1));
                } else if (epi == 3) {
                    v0 = (v0 - p2[n])   * rsqrtf(p3[n]   + EPSBN) * p0[n]   + p1[n];
                    v1 = (v1 - p2[n+1]) * rsqrtf(p3[n+1] + EPSBN) * p0[n+1] + p1[n+1];
                    v0 = fmaxf(v0 + addsrc[(size_t)mo * Ntot + n], 0.f);
                    v1 = fmaxf(v1 + addsrc[(size_t)mo * Ntot + n + 1], 0.f);
                }
                const size_t ob = (size_t)mo * Ntot + n;
                if (outF) *(float2*)&outF[ob] = make_float2(v0, v1);
                if (outH)
                    *(__half2*)&outH[ob] =
                        __halves2half2(__float2half_rn(v0), __float2half_rn(v1));
            }
}

// ====================== prep (x + all weights -> fp16), one launch ============
__global__ void __launch_bounds__(256) prep_all_kernel(
    const float* __restrict__ x,
    const float* __restrict__ Win, const float* __restrict__ ip,
    const float* __restrict__ xp,  const float* __restrict__ dtp,
    const float* __restrict__ op,  const float* __restrict__ Wo,
    __half* __restrict__ dx,
    __half* __restrict__ dWin, __half* __restrict__ dip,
    __half* __restrict__ dxp,  __half* __restrict__ ddtp,
    __half* __restrict__ dop,  __half* __restrict__ dWo)
{
    const int sx = NT * CC, s0 = CC * CC, s1 = 2 * DIN * CC, s2 = 64 * DIN,
              s3 = DIN * DTR, s4 = CC * DIN;
    int i = blockIdx.x * blockDim.x + threadIdx.x;
    if (i < sx) { dx[i]   = __float2half_rn(x[i]);   return; } i -= sx;
    if (i < s0) { dWin[i] = __float2half_rn(Win[i]); return; } i -= s0;
    if (i < s1) { dip[i]  = __float2half_rn(ip[i]);  return; } i -= s1;
    if (i < s2) { dxp[i]  = __float2half_rn(xp[i]);  return; } i -= s2;
    if (i < s3) { ddtp[i] = __float2half_rn(dtp[i]); return; } i -= s3;
    if (i < s4) { dop[i]  = __float2half_rn(op[i]);  return; } i -= s4;
    dWo[i] = __float2half_rn(Wo[i]);
}

// ---------- depthwise causal conv: register-blocked 8 rows x 2 channels -------
__global__ void __launch_bounds__(256) conv_silu_kernel(
    const __half2* __restrict__ xz2,
    const float* __restrict__ cw, const float* __restrict__ cb,
    __half2* __restrict__ xch2, __half2* __restrict__ uz)
{
    int g   = blockIdx.x * blockDim.x + threadIdx.x;  // over (NT/8)*(DIN/2)
    int dp  = g & (DIN / 2 - 1);
    int rg  = g >> 9;
    int row0 = rg * 8;
    int l0   = row0 & (LL - 1);
    int d    = dp * 2;

    const float bx  = cb[d],     by  = cb[d + 1];
    const float c0x = cw[d*4+0], c1x = cw[d*4+1], c2x = cw[d*4+2], c3x = cw[d*4+3];
    const float c0y = cw[d*4+4], c1y = cw[d*4+5], c2y = cw[d*4+6], c3y = cw[d*4+7];

    float2 w[11];
    #pragma unroll
    for (int j = 0; j < 11; j++) {
        int l = l0 - 3 + j;
        w[j] = (l >= 0)
             ? __half22float2(xz2[(long)(row0 - 3 + j) * DIN + dp])
             : make_float2(0.f, 0.f);
    }

    #pragma unroll
    for (int i = 0; i < 8; i++) {
        const long row = row0 + i;
        float ax = bx, ay = by;
        ax = fmaf(c0x, w[i].x,   ax); ay = fmaf(c0y, w[i].y,   ay);
        ax = fmaf(c1x, w[i+1].x, ax); ay = fmaf(c1y, w[i+1].y, ay);
        ax = fmaf(c2x, w[i+2].x, ax); ay = fmaf(c2y, w[i+2].y, ay);
        ax = fmaf(c3x, w[i+3].x, ax); ay = fmaf(c3y, w[i+3].y, ay);

        float ux = __fdividef(ax, 1.f + __expf(-ax));
        float uy = __fdividef(ay, 1.f + __expf(-ay));
        float2 zf = __half22float2(xz2[row * DIN + DIN / 2 + dp]);
        float gx = __fdividef(zf.x, 1.f + __expf(-zf.x));
        float gy = __fdividef(zf.y, 1.f + __expf(-zf.y));

        xch2[row * (DIN / 2) + dp] =
            __halves2half2(__float2half_rn(ux), __float2half_rn(uy));
        __half2 a = __halves2half2(__float2half_rn(ux), __float2half_rn(gx));
        __half2 b = __halves2half2(__float2half_rn(uy), __float2half_rn(gy));
        uint2 pk = make_uint2(*(uint32_t*)&a, *(uint32_t*)&b);
        *(uint2*)&uz[row * DIN + d] = pk;
    }
}

// ========================= chunked selective scan (v2) =========================
// warp = 4 d x 8 s-lanes, lane owns states 2sl, 2sl+1. Block = 64 thr = 8 d.
// B/C read directly from db16 (fp16, offsets +32 / +48, row stride 64).
#define SD 8
#define ST 64

// Phase 1: zero-init h-recurrence per chunk, stores h_end + S_end (chunks 0..2)
__global__ void __launch_bounds__(64) scan_pre_kernel(
    const __half* __restrict__ dtg, const __half* __restrict__ dbg,
    const __half* __restrict__ xcg, const float* __restrict__ A_log,
    float* __restrict__ hend, float* __restrict__ send)
{
    __shared__ __align__(16) __half  s_dt[3][ST][SD];
    __shared__ __align__(16) __half  s_u [3][ST][SD];
    __shared__ __align__(16) __half2 s_b [3][ST][8];

    const int tid  = threadIdx.x;
    const int warp = tid >> 5, lane = tid & 31;
    const int sl   = lane & 7, dl = lane >> 3;
    const int dg   = warp * 4 + dl;
    const int d0   = blockIdx.x * SD;
    const int d    = d0 + dg;
    const int b    = blockIdx.y;
    const int cz   = blockIdx.z;
    const long rbase = (long)b * LL + (long)cz * CHL;

    const float A0 = -expf(A_log[d * DS + 2 * sl]);

    auto stage_load = [&](int st, int buf) {
        const long row0 = rbase + (long)st * ST;
        #pragma unroll
        for (int j0 = 0; j0 < 256; j0 += 64) {
            int j = tid + j0;
            if (j < 64) {
                cpa16(smem_u32(&s_dt[buf][j][0]), dtg + (row0 + j) * DIN + d0);
            } else if (j < 128) {
                int r = j - 64;
                cpa16(smem_u32(&s_u[buf][r][0]), xcg + (row0 + r) * DIN + d0);
            } else {
                int v = j - 128, r = v >> 1, q = v & 1;
                cpa16(smem_u32(&s_b[buf][r][q * 4]),
                      dbg + (row0 + r) * 64 + 32 + q * 8);
            }
        }
    };

    stage_load(0, 0); CP_COMMIT;
    stage_load(1, 1); CP_COMMIT;

    float h0 = 0.f, h1 = 0.f, Sacc = 0.f;
    const int NST = CHL / ST;   // 8
    for (int ts = 0; ts < NST; ts++) {
        CP_WAIT1;
        __syncthreads();
        const int buf = ts % 3;
        if (ts + 2 < NST) stage_load(ts + 2, (ts + 2) % 3);
        CP_COMMIT;

        #pragma unroll
        for (int t = 0; t < ST; t++) {
            float  dtv = __half2float(s_dt[buf][t][dg]);
            float  ux  = __half2float(s_u[buf][t][dg]);
            float2 bv  = __half22float2(s_b[buf][t][sl]);
            float dA0 = __expf(dtv * A0);
            float q   = __shfl_sync(0xffffffffu, dA0, 0, 8);   // exp(-dt)
            float dA1 = dA0 * q;
            float cx = dtv * ux;
            h0 = fmaf(dA0, h0, cx * bv.x);
            h1 = fmaf(dA1, h1, cx * bv.y);
            Sacc += dtv;
        }
    }
    const size_t base = ((size_t)(cz * NB + b) * DIN + d) * DS + 2 * sl;
    *(float2*)&hend[base] = make_float2(h0, h1);
    if (sl == 0) send[(size_t)(cz * NB + b) * DIN + d] = Sacc;
}

// Phase 2: sequential chunk-init fix (tiny)
__global__ void __launch_bounds__(256) scan_fix_kernel(
    const float* __restrict__ hend, const float* __restrict__ send,
    const float* __restrict__ A_log, float* __restrict__ hinit)
{
    int i = blockIdx.x * blockDim.x + threadIdx.x;   // over NB*DIN*DS
    int s = i & 15, dd = (i >> 4) & (DIN - 1), b = i >> 14;
    const float Aa = -expf(A_log[dd * DS + s]);
    float hi = 0.f;
    hinit[((size_t)(0 * NB + b) * DIN + dd) * DS + s] = 0.f;
    #pragma unroll
    for (int c = 1; c < NCH; c++) {
        float he = hend[((size_t)((c - 1) * NB + b) * DIN + dd) * DS + s];
        float Se = send[(size_t)((c - 1) * NB + b) * DIN + dd];
        hi = he + __expf(Se * Aa) * hi;
        hinit[((size_t)(c * NB + b) * DIN + dd) * DS + s] = hi;
    }
}

// Phase 3: full scan per chunk, seeded with true h_init
__global__ void __launch_bounds__(64) scan_main_kernel(
    const __half* __restrict__ dtg, const __half* __restrict__ dbg,
    const __half2* __restrict__ uzg,
    const float* __restrict__ A_log, const float* __restrict__ Dp,
    const float* __restrict__ hinit, __half* __restrict__ yh)
{
    __shared__ __align__(16) __half  s_dt[3][ST][SD];
    __shared__ __align__(16) __half2 s_uz[3][ST][SD];
    __shared__ __align__(16) __half2 s_b [3][ST][8];
    __shared__ __align__(16) __half2 s_c [3][ST][8];
    __shared__ __align__(16) __half  s_y [2][ST][SD];

    const int tid  = threadIdx.x;
    const int warp = tid >> 5, lane = tid & 31;
    const int sl   = lane & 7, dl = lane >> 3;
    const int dg   = warp * 4 + dl;
    const int d0   = blockIdx.x * SD;
    const int d    = d0 + dg;
    const int b    = blockIdx.y;
    const int cz   = blockIdx.z;
    const long rbase = (long)b * LL + (long)cz * CHL;

    const float A0 = -expf(A_log[d * DS + 2 * sl]);
    const float Dd = Dp[d];

    auto stage_load = [&](int st, int buf) {
        const long row0 = rbase + (long)st * ST;
        #pragma unroll
        for (int j0 = 0; j0 < 448; j0 += 64) {
            int j = tid + j0;
            if (j < 64) {
                cpa16(smem_u32(&s_dt[buf][j][0]), dtg + (row0 + j) * DIN + d0);
            } else if (j < 192) {
                int u = j - 64, r = u >> 1, q = u & 1;
                cpa16(smem_u32(&s_uz[buf][r][q * 4]),
                      uzg + (row0 + r) * DIN + d0 + q * 4);
            } else if (j < 320) {
                int v = j - 192, r = v >> 1, q = v & 1;
                cpa16(smem_u32(&s_b[buf][r][q * 4]),
                      dbg + (row0 + r) * 64 + 32 + q * 8);
            } else {
                int v = j - 320, r = v >> 1, q = v & 1;
                cpa16(smem_u32(&s_c[buf][r][q * 4]),
                      dbg + (row0 + r) * 64 + 48 + q * 8);
            }
        }
    };
    auto flush_y = [&](int st, int yb) {
        const long row0 = rbase + (long)st * ST;
        // 64 rows x 16B = 256 u32 / 64 thr
        #pragma unroll
        for (int j0 = 0; j0 < 256; j0 += 64) {
            int j = tid + j0;
            int r = j >> 2, w = j & 3;
            uint32_t val = ((const uint32_t*)&s_y[yb][r][0])[w];
            *(uint32_t*)(yh + (row0 + r) * DIN + d0 + w * 2) = val;
        }
    };

    stage_load(0, 0); CP_COMMIT;
    stage_load(1, 1); CP_COMMIT;

    float2 h00 = *(const float2*)&hinit[((size_t)(cz * NB + b) * DIN + d) * DS + 2 * sl];
    float h0 = h00.x, h1 = h00.y;

    const int NST = CHL / ST;   // 8
    for (int ts = 0; ts < NST; ts++) {
        CP_WAIT1;
        __syncthreads();
        if (ts > 0) flush_y(ts - 1, (ts - 1) & 1);
        const int buf = ts % 3;
        if (ts + 2 < NST) stage_load(ts + 2, (ts + 2) % 3);
        CP_COMMIT;

        const int yb = ts & 1;
        #pragma unroll
        for (int t8 = 0; t8 < ST; t8 += 8) {
            float p8[8], g8[8];
            #pragma unroll
            for (int i = 0; i < 8; i++) {
                const int t = t8 + i;
                float  dtv = __half2float(s_dt[buf][t][dg]);
                float2 uzv = __half22float2(s_uz[buf][t][dg]);
                float2 bv  = __half22float2(s_b[buf][t][sl]);
                float2 cv  = __half22float2(s_c[buf][t][sl]);
                float dA0 = __expf(dtv * A0);
                float q   = __shfl_sync(0xffffffffu, dA0, 0, 8);  // exp(-dt)
                float dA1 = dA0 * q;
                float cx = dtv * uzv.x;
                h0 = fmaf(dA0, h0, cx * bv.x);
                h1 = fmaf(dA1, h1, cx * bv.y);
                float p = fmaf(h1, cv.y, h0 * cv.x);
                if (sl == 0) p = fmaf(uzv.x, Dd, p);
                p8[i] = p;
                g8[i] = uzv.y;
            }
            #pragma unroll
            for (int i = 0; i < 8; i += 2) {
                __half2 pp = __halves2half2(__float2half_rn(p8[i]),
                                            __float2half_rn(p8[i+1]));
                uint32_t u = *(uint32_t*)&pp;
                #pragma unroll
                for (int k = 4; k >= 1; k >>= 1) {
                    uint32_t v = __shfl_xor_sync(0xffffffffu, u, k, 8);
                    __half2 va = *(__half2*)&u, vb = *(__half2*)&v;
                    va = __hadd2(va, vb);
                    u = *(uint32_t*)&va;
                }
                if (sl == 0) {
                    __half2 r = *(__half2*)&u;
                    s_y[yb][t8 + i][dg] =
                        __hmul(__low2half(r),  __float2half_rn(g8[i]));
                    s_y[yb][t8 + i + 1][dg] =
                        __hmul(__high2half(r), __float2half_rn(g8[i+1]));
                }
            }
        }
    }
    __syncthreads();
    flush_y(NST - 1, (NST - 1) & 1);
}

// ---------------- launch -------------------------------------------------------
extern "C" void kernel_launch(void* const* d_in, const int* in_sizes, int n_in,
                              void* d_out, int out_size)
{
    const float* x          = (const float*)d_in[1];
    const int*   order      = (const int*)  d_in[3];
    const int*   inv        = (const int*)  d_in[4];
    const float* W_in       = (const float*)d_in[5];
    const float* bn_in_g    = (const float*)d_in[6];
    const float* bn_in_b    = (const float*)d_in[7];
    const float* bn_in_m    = (const float*)d_in[8];
    const float* bn_in_v    = (const float*)d_in[9];
    const float* in_proj_w  = (const float*)d_in[10];
    const float* conv_w     = (const float*)d_in[11];
    const float* conv_b     = (const float*)d_in[12];
    const float* x_proj_w   = (const float*)d_in[13];
    const float* dt_proj_w  = (const float*)d_in[14];
    const float* dt_proj_b  = (const float*)d_in[15];
    const float* A_log      = (const float*)d_in[16];
    const float* Dp         = (const float*)d_in[17];
    const float* out_proj_w = (const float*)d_in[18];
    const float* W_out      = (const float*)d_in[19];
    const float* bn_o_g     = (const float*)d_in[20];
    const float* bn_o_b     = (const float*)d_in[21];
    const float* bn_o_m     = (const float*)d_in[22];
    const float* bn_o_v     = (const float*)d_in[23];
    float* out = (float*)d_out;

    __half *x16, *hg16, *xz16, *xc16, *db16, *dt16, *y16, *og16;
    __half2 *uz16;
    float *hend, *send, *hinit;
    __half *Winh, *iph, *xph, *dtph, *oph, *Woh;
    cudaGetSymbolAddress((void**)&x16,  g_x16);
    cudaGetSymbolAddress((void**)&hg16, g_hg16);
    cudaGetSymbolAddress((void**)&xz16, g_xz16);
    cudaGetSymbolAddress((void**)&xc16, g_xc16);
    cudaGetSymbolAddress((void**)&db16, g_db16);
    cudaGetSymbolAddress((void**)&dt16, g_dt16);
    cudaGetSymbolAddress((void**)&uz16, g_uz16);
    cudaGetSymbolAddress((void**)&y16,  g_y16);
    cudaGetSymbolAddress((void**)&og16, g_og16);
    cudaGetSymbolAddress((void**)&hend, g_hend);
    cudaGetSymbolAddress((void**)&send, g_send);
    cudaGetSymbolAddress((void**)&hinit,g_hinit);
    cudaGetSymbolAddress((void**)&Winh, g_Win_h);
    cudaGetSymbolAddress((void**)&iph,  g_ip_h);
    cudaGetSymbolAddress((void**)&xph,  g_xp_h);
    cudaGetSymbolAddress((void**)&dtph, g_dtp_h);
    cudaGetSymbolAddress((void**)&oph,  g_op_h);
    cudaGetSymbolAddress((void**)&Woh,  g_Wo_h);

    const int SMEM_BIG   = 4 * (128 + 128) * 80;   // 81920
    const int SMEM_SMALL = 4 * (64 + 64) * 80;     // 40960
    cudaFuncSetAttribute((const void*)gemm_fp16<128,128,4,2>,
                         cudaFuncAttributeMaxDynamicSharedMemorySize, SMEM_BIG);
    cudaFuncSetAttribute((const void*)gemm_fp16<64,64,2,4>,
                         cudaFuncAttributeMaxDynamicSharedMemorySize, SMEM_SMALL);

    // prep (x + weights) in one launch
    {
        const int total = NT*CC + CC*CC + 2*DIN*CC + 64*DIN + DIN*DTR + CC*DIN + CC*CC;
        prep_all_kernel<<<(total + 255) / 256, 256>>>(
            x, W_in, in_proj_w, x_proj_w, dt_proj_w, out_proj_w, W_out,
            x16, Winh, iph, xph, dtph, oph, Woh);
    }

    // 1) hg = fp16(relu(BN(x @ W_in^T))) scattered by inv  ==  h[order]
    gemm_fp16<128,128,4,2><<<dim3(CC/128, NT/128), 256, SMEM_BIG>>>(
        x16, CC, Winh, CC, nullptr, hg16, inv, CC, 1,
        bn_in_g, bn_in_b, bn_in_m, bn_in_v, nullptr);

    // 2) xz = hg @ in_proj_w^T   (fp16)
    gemm_fp16<128,128,4,2><<<dim3(2*DIN/128, NT/128), 256, SMEM_BIG>>>(
        hg16, CC, iph, CC, nullptr, xz16, nullptr, 2*DIN, 0,
        nullptr, nullptr, nullptr, nullptr, nullptr);

    // 3) xc16 + packed {u, gate}
    conv_silu_kernel<<<(NT / 8) * (DIN / 2) / 256, 256>>>(
        (const __half2*)xz16, conv_w, conv_b, (__half2*)xc16, uz16);

    // 4) db16 = fp16(xc @ x_proj_w^T), N=64  (B at +32, C at +48 read in place)
    gemm_fp16<64,64,2,4><<<dim3(1, NT/64), 256, SMEM_SMALL>>>(
        xc16, DIN, xph, DIN, nullptr, db16, nullptr, 64, 0,
        nullptr, nullptr, nullptr, nullptr, nullptr);

    // 5) dt16 = fp16(softplus(dt_low @ dt_proj_w^T + b)), K=32 (lda=64)
    gemm_fp16<128,128,4,2><<<dim3(DIN/128, NT/128), 256, SMEM_BIG>>>(
        db16, 64, dtph, DTR, nullptr, dt16, nullptr, DIN, 2,
        dt_proj_b, nullptr, nullptr, nullptr, nullptr);

    // 6) chunked selective scan (v2)
    scan_pre_kernel<<<dim3(DIN / SD, NB, NCH - 1), 64>>>(
        dt16, db16, xc16, A_log, hend, send);
    scan_fix_kernel<<<NB * DIN * DS / 256, 256>>>(hend, send, A_log, hinit);
    scan_main_kernel<<<dim3(DIN / SD, NB, NCH), 64>>>(
        dt16, db16, uz16, A_log, Dp, hinit, y16);

    // 7) og = fp16(y @ out_proj_w^T) scattered by order == o1[inv]
    gemm_fp16<128,128,4,2><<<dim3(CC/128, NT/128), 256, SMEM_BIG>>>(
        y16, DIN, oph, DIN, nullptr, og16, order, CC, 0,
        nullptr, nullptr, nullptr, nullptr, nullptr);

    // 8) out = relu(BN(og @ W_out^T) + x)
    gemm_fp16<128,128,4,2><<<dim3(CC/128, NT/128), 256, SMEM_BIG>>>(
        og16, CC, Woh, CC, out, nullptr, nullptr, CC, 3,
        bn_o_g, bn_o_b, bn_o_m, bn_o_v, x);
}

// round 15
// speedup vs baseline: 1.0394x; 1.0394x over previous
#include <cuda_runtime.h>
#include <cuda_fp16.h>
#include <math.h>
#include <stdint.h>

// Problem constants
#define NB 4
#define LL 2048
#define CC 512
#define DIN 1024
#define DS 16
#define DCONV 4
#define DTR 32
#define NT (NB * LL)   // 8192 rows
#define EPSBN 1e-5f

// ---------------- scratch (device globals; no allocation allowed) -------------
__device__ __align__(256) __half  g_x16 [NT * CC];
__device__ __align__(256) __half  g_hg16[NT * CC];
__device__ __align__(256) __half  g_xz16[NT * 2 * DIN];
__device__ __align__(256) __half  g_xc16[NT * DIN];
__device__ __align__(256) __half  g_db16[NT * 64];
__device__ __align__(256) __half  g_dt16[NT * DIN];
__device__ __align__(256) __half2 g_uz16[NT * DIN];   // {silu(u), silu(z)}
__device__ __align__(256) float2  g_bq  [NT * 8];     // {B_2sl, B_2sl+1}
__device__ __align__(256) float2  g_cq  [NT * 8];     // {C_2sl, C_2sl+1}
__device__ __align__(256) __half  g_y16 [NT * DIN];
__device__ __align__(256) __half  g_og16[NT * CC];
// fp16 weights
__device__ __align__(256) __half g_Win_h[CC * CC];
__device__ __align__(256) __half g_ip_h [2 * DIN * CC];
__device__ __align__(256) __half g_xp_h [64 * DIN];
__device__ __align__(256) __half g_dtp_h[DIN * DTR];
__device__ __align__(256) __half g_op_h [CC * DIN];
__device__ __align__(256) __half g_Wo_h [CC * CC];

// ============================ PTX helpers =====================================
__device__ __forceinline__ uint32_t smem_u32(const void* p) {
    uint32_t a;
    asm("{ .reg .u64 t; cvta.to.shared.u64 t, %1; cvt.u32.u64 %0, t; }"
        : "=r"(a) : "l"(p));
    return a;
}
__device__ __forceinline__ void cpa16(uint32_t d, const void* s) {
    asm volatile("cp.async.cg.shared.global [%0], [%1], 16;" :: "r"(d), "l"(s));
}
#define CP_COMMIT asm volatile("cp.async.commit_group;" ::: "memory")
#define CP_WAIT1  asm volatile("cp.async.wait_group 1;"  ::: "memory")
#define CP_WAIT2  asm volatile("cp.async.wait_group 2;"  ::: "memory")

__device__ __forceinline__ void ldsm4(uint32_t* r, uint32_t a) {
    asm volatile("ldmatrix.sync.aligned.m8n8.x4.shared.b16 {%0,%1,%2,%3}, [%4];"
        : "=r"(r[0]), "=r"(r[1]), "=r"(r[2]), "=r"(r[3]) : "r"(a));
}
__device__ __forceinline__ void mma16816(float* c, const uint32_t* a, const uint32_t* b) {
    asm volatile(
        "mma.sync.aligned.m16n8k16.row.col.f32.f16.f16.f32 "
        "{%0,%1,%2,%3}, {%4,%5,%6,%7}, {%8,%9}, {%0,%1,%2,%3};"
        : "+f"(c[0]), "+f"(c[1]), "+f"(c[2]), "+f"(c[3])
        : "r"(a[0]), "r"(a[1]), "r"(a[2]), "r"(a[3]), "r"(b[0]), "r"(b[1]));
}

// ====================== single-term fp16 HMMA GEMM ============================
// C[M,N] = epi( A[M,K] @ W[N,K]^T ). CTA MT x NTILE, 256 thr, 8 warps
// (WMW x WNW), 4-stage cp.async pipeline, MINB CTAs/SM.
template <int MT, int NTILE>
__device__ __forceinline__ void load_stage(
    uint32_t base, int tid, int m0, int n0, int lda, int K, int c,
    const __half* A, const __half* W)
{
    const int k0 = c * 32;
    #pragma unroll
    for (int e = 0; e < MT * 4 / 256; e++) {
        int t = tid + e * 256;
        int r = t >> 2, g = t & 3;
        cpa16(base + r * 80 + g * 16, A + (size_t)(m0 + r) * lda + k0 + g * 8);
    }
    uint32_t dw = base + (uint32_t)MT * 80;
    #pragma unroll
    for (int e = 0; e < NTILE * 4 / 256; e++) {
        int t = tid + e * 256;
        int r = t >> 2, g = t & 3;
        cpa16(dw + r * 80 + g * 16, W + (size_t)(n0 + r) * K + k0 + g * 8);
    }
}

template <int MT, int NTILE, int WMW, int WNW, int MINB>
__global__ void __launch_bounds__(256, MINB) gemm_fp16(
    const __half* __restrict__ A, int lda,
    const __half* __restrict__ W, int K,
    float* __restrict__ outF, __half* __restrict__ outH,
    const int* __restrict__ scat, int Ntot, int epi,
    const float* __restrict__ p0, const float* __restrict__ p1,
    const float* __restrict__ p2, const float* __restrict__ p3,
    const float* __restrict__ addsrc)
{
    constexpr int WTM = MT / WMW;
    constexpr int WTN = NTILE / WNW;
    constexpr int MTFR = WTM / 16;
    constexpr int NT8 = WTN / 8;
    constexpr int STAGE = (MT + NTILE) * 80;

    extern __shared__ __align__(128) char smraw[];
    const uint32_t sb = smem_u32(smraw);

    const int tid = threadIdx.x;
    const int lane = tid & 31, warp = tid >> 5;
    const int wm = warp % WMW, wn = warp / WMW;
    const int m0 = blockIdx.y * MT;
    const int n0 = blockIdx.x * NTILE;

    float acc[MTFR][NT8][4] = {};

    const int nch = K >> 5;
    #pragma unroll
    for (int s = 0; s < 3; s++) {
        if (s < nch)
            load_stage<MT, NTILE>(sb + s * STAGE, tid, m0, n0, lda, K, s, A, W);
        CP_COMMIT;
    }

    const int lr = lane & 15;
    const int lc = (lane >> 4) << 3;

    for (int c = 0; c < nch; c++) {
        CP_WAIT2;
        __syncthreads();
        {
            int cn = c + 3;
            if (cn < nch)
                load_stage<MT, NTILE>(sb + (cn & 3) * STAGE, tid, m0, n0, lda, K, cn, A, W);
            CP_COMMIT;
        }
        const uint32_t cur = sb + (uint32_t)(c & 3) * STAGE;
        #pragma unroll
        for (int kk = 0; kk < 32; kk += 16) {
            uint32_t af[MTFR][4];
            #pragma unroll
            for (int mt = 0; mt < MTFR; mt++)
                ldsm4(af[mt], cur + (uint32_t)((wm * WTM + mt * 16 + lr) * 80 + (kk + lc) * 2));
            uint32_t wf[NT8][2];
            #pragma unroll
            for (int p = 0; p < NT8 / 2; p++) {
                uint32_t a = cur + (uint32_t)((MT + wn * WTN + p * 16 + lr) * 80 + (kk + lc) * 2);
                uint32_t r4[4];
                ldsm4(r4, a);
                wf[2*p][0] = r4[0]; wf[2*p][1] = r4[2];
                wf[2*p+1][0] = r4[1]; wf[2*p+1][1] = r4[3];
            }
            #pragma unroll
            for (int mt = 0; mt < MTFR; mt++)
                #pragma unroll
                for (int nt = 0; nt < NT8; nt++)
                    mma16816(acc[mt][nt], af[mt], wf[nt]);
        }
    }

    const int g = lane >> 2, tg = lane & 3;
    #pragma unroll
    for (int mt = 0; mt < MTFR; mt++)
        #pragma unroll
        for (int nt = 0; nt < NT8; nt++)
            #pragma unroll
            for (int rr = 0; rr < 2; rr++) {
                int m = m0 + wm * WTM + mt * 16 + g + rr * 8;
                int n = n0 + wn * WTN + nt * 8 + tg * 2;
                int mo = scat ? scat[m] : m;
                float v0 = acc[mt][nt][rr * 2 + 0];
                float v1 = acc[mt][nt][rr * 2 + 1];
                if (epi == 1) {
                    v0 = fmaxf((v0 - p2[n])   * rsqrtf(p3[n]   + EPSBN) * p0[n]   + p1[n],   0.f);
                    v1 = fmaxf((v1 - p2[n+1]) * rsqrtf(p3[n+1] + EPSBN) * p0[n+1] + p1[n+1], 0.f);
                } else if (epi == 2) {
                    v0 += p0[n];   v0 = (v0 > 20.f) ? v0 : __logf(1.f + __expf(v0));
                    v1 += p0[n+1]; v1 = (v1 > 20.f) ? v1 : __logf(1.f + __expf(v1));
                } else if (epi == 3) {
                    v0 = (v0 - p2[n])   * rsqrtf(p3[n]   + EPSBN) * p0[n]   + p1[n];
                    v1 = (v1 - p2[n+1]) * rsqrtf(p3[n+1] + EPSBN) * p0[n+1] + p1[n+1];
                    v0 = fmaxf(v0 + addsrc[(size_t)mo * Ntot + n], 0.f);
                    v1 = fmaxf(v1 + addsrc[(size_t)mo * Ntot + n + 1], 0.f);
                }
                const size_t ob = (size_t)mo * Ntot + n;
                if (outF) *(float2*)&outF[ob] = make_float2(v0, v1);
                if (outH)
                    *(__half2*)&outH[ob] =
                        __halves2half2(__float2half_rn(v0), __float2half_rn(v1));
            }
}

// ====================== prep (x + all weights -> fp16), one launch ============
__global__ void __launch_bounds__(256) prep_all_kernel(
    const float* __restrict__ x,
    const float* __restrict__ Win, const float* __restrict__ ip,
    const float* __restrict__ xp,  const float* __restrict__ dtp,
    const float* __restrict__ op,  const float* __restrict__ Wo,
    __half* __restrict__ dx,
    __half* __restrict__ dWin, __half* __restrict__ dip,
    __half* __restrict__ dxp,  __half* __restrict__ ddtp,
    __half* __restrict__ dop,  __half* __restrict__ dWo)
{
    const int sx = NT * CC, s0 = CC * CC, s1 = 2 * DIN * CC, s2 = 64 * DIN,
              s3 = DIN * DTR, s4 = CC * DIN;
    int i = blockIdx.x * blockDim.x + threadIdx.x;
    if (i < sx) { dx[i]   = __float2half_rn(x[i]);   return; } i -= sx;
    if (i < s0) { dWin[i] = __float2half_rn(Win[i]); return; } i -= s0;
    if (i < s1) { dip[i]  = __float2half_rn(ip[i]);  return; } i -= s1;
    if (i < s2) { dxp[i]  = __float2half_rn(xp[i]);  return; } i -= s2;
    if (i < s3) { ddtp[i] = __float2half_rn(dtp[i]); return; } i -= s3;
    if (i < s4) { dop[i]  = __float2half_rn(op[i]);  return; } i -= s4;
    dWo[i] = __float2half_rn(Wo[i]);
}

// BC pack: db16[row][32+2sl..] -> bq[row][sl] = {B_2sl, B_2sl+1} (fp32), cq same
__global__ void __launch_bounds__(256) pack_bc_kernel(
    const __half* __restrict__ db16, float2* __restrict__ bq,
    float2* __restrict__ cq)
{
    int i = blockIdx.x * blockDim.x + threadIdx.x;   // over NT*8
    int sl = i & 7, row = i >> 3;
    const __half* p = db16 + (size_t)row * 64 + DTR;
    bq[i] = make_float2(__half2float(p[2*sl]),      __half2float(p[2*sl + 1]));
    cq[i] = make_float2(__half2float(p[DS + 2*sl]), __half2float(p[DS + 2*sl + 1]));
}

// ---------- depthwise causal conv: register-blocked 8 rows x 2 channels -------
__global__ void __launch_bounds__(256) conv_silu_kernel(
    const __half2* __restrict__ xz2,
    const float* __restrict__ cw, const float* __restrict__ cb,
    __half2* __restrict__ xch2, __half2* __restrict__ uz)
{
    int g   = blockIdx.x * blockDim.x + threadIdx.x;  // over (NT/8)*(DIN/2)
    int dp  = g & (DIN / 2 - 1);
    int rg  = g >> 9;
    int row0 = rg * 8;
    int l0   = row0 & (LL - 1);
    int d    = dp * 2;

    const float bx  = cb[d],     by  = cb[d + 1];
    const float c0x = cw[d*4+0], c1x = cw[d*4+1], c2x = cw[d*4+2], c3x = cw[d*4+3];
    const float c0y = cw[d*4+4], c1y = cw[d*4+5], c2y = cw[d*4+6], c3y = cw[d*4+7];

    float2 w[11];
    #pragma unroll
    for (int j = 0; j < 11; j++) {
        int l = l0 - 3 + j;
        w[j] = (l >= 0)
             ? __half22float2(xz2[(long)(row0 - 3 + j) * DIN + dp])
             : make_float2(0.f, 0.f);
    }

    #pragma unroll
    for (int i = 0; i < 8; i++) {
        const long row = row0 + i;
        float ax = bx, ay = by;
        ax = fmaf(c0x, w[i].x,   ax); ay = fmaf(c0y, w[i].y,   ay);
        ax = fmaf(c1x, w[i+1].x, ax); ay = fmaf(c1y, w[i+1].y, ay);
        ax = fmaf(c2x, w[i+2].x, ax); ay = fmaf(c2y, w[i+2].y, ay);
        ax = fmaf(c3x, w[i+3].x, ax); ay = fmaf(c3y, w[i+3].y, ay);

        float ux = __fdividef(ax, 1.f + __expf(-ax));
        float uy = __fdividef(ay, 1.f + __expf(-ay));
        float2 zf = __half22float2(xz2[row * DIN + DIN / 2 + dp]);
        float gx = __fdividef(zf.x, 1.f + __expf(-zf.x));
        float gy = __fdividef(zf.y, 1.f + __expf(-zf.y));

        xch2[row * (DIN / 2) + dp] =
            __halves2half2(__float2half_rn(ux), __float2half_rn(uy));
        __half2 a = __halves2half2(__float2half_rn(ux), __float2half_rn(gx));
        __half2 b = __halves2half2(__float2half_rn(uy), __float2half_rn(gy));
        uint2 pk = make_uint2(*(uint32_t*)&a, *(uint32_t*)&b);
        *(uint2*)&uz[row * DIN + d] = pk;
    }
}

// ---------------- selective scan: 2 states/lane, 4 d/warp (R12 version) -------
#define SD 8
#define ST 64

__global__ void __launch_bounds__(64) scan_kernel(
    const __half* __restrict__ dtg, const float2* __restrict__ bqg,
    const float2* __restrict__ cqg, const __half2* __restrict__ uzg,
    const float* __restrict__ A_log, const float* __restrict__ Dp,
    __half* __restrict__ yh)
{
    __shared__ __align__(16) __half  s_dt[3][ST][SD];
    __shared__ __align__(16) __half2 s_uz[3][ST][SD];
    __shared__ __align__(16) float2  s_b[3][ST][8];
    __shared__ __align__(16) float2  s_c[3][ST][8];
    __shared__ __align__(16) __half  s_y[2][ST][SD];

    const int tid  = threadIdx.x;
    const int warp = tid >> 5, lane = tid & 31;
    const int sl   = lane & 7, dl = lane >> 3;
    const int dg   = warp * 4 + dl;
    const int d0   = blockIdx.x * SD;
    const int d    = d0 + dg;
    const long rbase = (long)blockIdx.y * LL;

    const float A0 = -expf(A_log[d * DS + 2 * sl]);
    const float A1 = -expf(A_log[d * DS + 2 * sl + 1]);
    const float Dd = Dp[d];

    auto stage_load = [&](int st, int buf) {
        const long row0 = rbase + (long)st * ST;
        for (int j = tid; j < 704; j += 64) {
            if (j < 64) {
                cpa16(smem_u32(&s_dt[buf][j][0]), dtg + (row0 + j) * DIN + d0);
            } else if (j < 192) {
                int u = j - 64, r = u >> 1, q = u & 1;
                cpa16(smem_u32(&s_uz[buf][r][q * 4]),
                      uzg + (row0 + r) * DIN + d0 + q * 4);
            } else if (j < 448) {
                int v = j - 192, r = v >> 2, q = v & 3;
                cpa16(smem_u32(&s_b[buf][r][q * 2]), bqg + (row0 + r) * 8 + q * 2);
            } else {
                int v = j - 448, r = v >> 2, q = v & 3;
                cpa16(smem_u32(&s_c[buf][r][q * 2]), cqg + (row0 + r) * 8 + q * 2);
            }
        }
    };
    auto flush_y = [&](int st, int yb) {
        const long row0 = rbase + (long)st * ST;
        #pragma unroll
        for (int j0 = 0; j0 < 256; j0 += 64) {
            int j = tid + j0;
            int r = j >> 2, w = j & 3;
            uint32_t val = ((const uint32_t*)&s_y[yb][r][0])[w];
            *(uint32_t*)(yh + (row0 + r) * DIN + d0 + w * 2) = val;
        }
    };

    stage_load(0, 0); CP_COMMIT;
    stage_load(1, 1); CP_COMMIT;

    float h0 = 0.f, h1 = 0.f;
    const int NST = LL / ST;   // 32
    for (int ts = 0; ts < NST; ts++) {
        CP_WAIT1;
        __syncthreads();
        if (ts > 0) flush_y(ts - 1, (ts - 1) & 1);
        const int buf = ts % 3;
        if (ts + 2 < NST) stage_load(ts + 2, (ts + 2) % 3);
        CP_COMMIT;

        const int yb = ts & 1;
        #pragma unroll
        for (int t8 = 0; t8 < ST; t8 += 8) {
            float p8[8], g8[8];
            #pragma unroll
            for (int i = 0; i < 8; i++) {
                const int t = t8 + i;
                float  dtv = __half2float(s_dt[buf][t][dg]);
                float2 uzv = __half22float2(s_uz[buf][t][dg]);
                float2 bv  = s_b[buf][t][sl];
                float2 cv  = s_c[buf][t][sl];
                float dA0 = __expf(dtv * A0);
                float dA1 = __expf(dtv * A1);
                float cx = dtv * uzv.x;
                h0 = fmaf(dA0, h0, cx * bv.x);
                h1 = fmaf(dA1, h1, cx * bv.y);
                float p = fmaf(h1, cv.y, h0 * cv.x);
                if (sl == 0) p = fmaf(uzv.x, Dd, p);
                p8[i] = p;
                g8[i] = uzv.y;
            }
            #pragma unroll
            for (int i = 0; i < 8; i += 2) {
                __half2 pp = __halves2half2(__float2half_rn(p8[i]),
                                            __float2half_rn(p8[i+1]));
                uint32_t u = *(uint32_t*)&pp;
                #pragma unroll
                for (int k = 4; k >= 1; k >>= 1) {
                    uint32_t v = __shfl_xor_sync(0xffffffffu, u, k, 8);
                    __half2 va = *(__half2*)&u, vb = *(__half2*)&v;
                    va = __hadd2(va, vb);
                    u = *(uint32_t*)&va;
                }
                if (sl == 0) {
                    __half2 r = *(__half2*)&u;
                    s_y[yb][t8 + i][dg] =
                        __hmul(__low2half(r),  __float2half_rn(g8[i]));
                    s_y[yb][t8 + i + 1][dg] =
                        __hmul(__high2half(r), __float2half_rn(g8[i+1]));
                }
            }
        }
    }
    __syncthreads();
    flush_y(NST - 1, (NST - 1) & 1);
}

// ---------------- launch -------------------------------------------------------
extern "C" void kernel_launch(void* const* d_in, const int* in_sizes, int n_in,
                              void* d_out, int out_size)
{
    const float* x          = (const float*)d_in[1];
    const int*   order      = (const int*)  d_in[3];
    const int*   inv        = (const int*)  d_in[4];
    const float* W_in       = (const float*)d_in[5];
    const float* bn_in_g    = (const float*)d_in[6];
    const float* bn_in_b    = (const float*)d_in[7];
    const float* bn_in_m    = (const float*)d_in[8];
    const float* bn_in_v    = (const float*)d_in[9];
    const float* in_proj_w  = (const float*)d_in[10];
    const float* conv_w     = (const float*)d_in[11];
    const float* conv_b     = (const float*)d_in[12];
    const float* x_proj_w   = (const float*)d_in[13];
    const float* dt_proj_w  = (const float*)d_in[14];
    const float* dt_proj_b  = (const float*)d_in[15];
    const float* A_log      = (const float*)d_in[16];
    const float* Dp         = (const float*)d_in[17];
    const float* out_proj_w = (const float*)d_in[18];
    const float* W_out      = (const float*)d_in[19];
    const float* bn_o_g     = (const float*)d_in[20];
    const float* bn_o_b     = (const float*)d_in[21];
    const float* bn_o_m     = (const float*)d_in[22];
    const float* bn_o_v     = (const float*)d_in[23];
    float* out = (float*)d_out;

    __half *x16, *hg16, *xz16, *xc16, *db16, *dt16, *y16, *og16;
    __half2 *uz16;
    float2 *bq, *cq;
    __half *Winh, *iph, *xph, *dtph, *oph, *Woh;
    cudaGetSymbolAddress((void**)&x16,  g_x16);
    cudaGetSymbolAddress((void**)&hg16, g_hg16);
    cudaGetSymbolAddress((void**)&xz16, g_xz16);
    cudaGetSymbolAddress((void**)&xc16, g_xc16);
    cudaGetSymbolAddress((void**)&db16, g_db16);
    cudaGetSymbolAddress((void**)&dt16, g_dt16);
    cudaGetSymbolAddress((void**)&uz16, g_uz16);
    cudaGetSymbolAddress((void**)&bq,   g_bq);
    cudaGetSymbolAddress((void**)&cq,   g_cq);
    cudaGetSymbolAddress((void**)&y16,  g_y16);
    cudaGetSymbolAddress((void**)&og16, g_og16);
    cudaGetSymbolAddress((void**)&Winh, g_Win_h);
    cudaGetSymbolAddress((void**)&iph,  g_ip_h);
    cudaGetSymbolAddress((void**)&xph,  g_xp_h);
    cudaGetSymbolAddress((void**)&dtph, g_dtp_h);
    cudaGetSymbolAddress((void**)&oph,  g_op_h);
    cudaGetSymbolAddress((void**)&Woh,  g_Wo_h);

    const int SMEM_128 = 4 * (128 + 128) * 80;   // 81920
    const int SMEM_64N128 = 4 * (64 + 128) * 80; // 61440
    const int SMEM_64  = 4 * (64 + 64) * 80;     // 40960
    cudaFuncSetAttribute((const void*)gemm_fp16<128,128,4,2,2>,
                         cudaFuncAttributeMaxDynamicSharedMemorySize, SMEM_128);
    cudaFuncSetAttribute((const void*)gemm_fp16<64,128,2,4,3>,
                         cudaFuncAttributeMaxDynamicSharedMemorySize, SMEM_64N128);
    cudaFuncSetAttribute((const void*)gemm_fp16<64,64,2,4,3>,
                         cudaFuncAttributeMaxDynamicSharedMemorySize, SMEM_64);

    // prep (x + weights) in one launch
    {
        const int total = NT*CC + CC*CC + 2*DIN*CC + 64*DIN + DIN*DTR + CC*DIN + CC*CC;
        prep_all_kernel<<<(total + 255) / 256, 256>>>(
            x, W_in, in_proj_w, x_proj_w, dt_proj_w, out_proj_w, W_out,
            x16, Winh, iph, xph, dtph, oph, Woh);
    }

    // 1) hg = fp16(relu(BN(x @ W_in^T))) scattered by inv  ==  h[order]
    gemm_fp16<64,128,2,4,3><<<dim3(CC/128, NT/64), 256, SMEM_64N128>>>(
        x16, CC, Winh, CC, nullptr, hg16, inv, CC, 1,
        bn_in_g, bn_in_b, bn_in_m, bn_in_v, nullptr);

    // 2) xz = hg @ in_proj_w^T   (fp16, multi-wave, throughput-bound)
    gemm_fp16<128,128,4,2,2><<<dim3(2*DIN/128, NT/128), 256, SMEM_128>>>(
        hg16, CC, iph, CC, nullptr, xz16, nullptr, 2*DIN, 0,
        nullptr, nullptr, nullptr, nullptr, nullptr);

    // 3) xc16 + packed {u, gate}
    conv_silu_kernel<<<(NT / 8) * (DIN / 2) / 256, 256>>>(
        (const __half2*)xz16, conv_w, conv_b, (__half2*)xc16, uz16);

    // 4) db16 = fp16(xc @ x_proj_w^T), N=64
    gemm_fp16<64,64,2,4,3><<<dim3(1, NT/64), 256, SMEM_64>>>(
        xc16, DIN, xph, DIN, nullptr, db16, nullptr, 64, 0,
        nullptr, nullptr, nullptr, nullptr, nullptr);

    // 4b) pack {B,C} pairs (fp32)
    pack_bc_kernel<<<NT * 8 / 256, 256>>>(db16, bq, cq);

    // 5) dt16 = fp16(softplus(dt_low @ dt_proj_w^T + b)), K=32 (lda=64)
    gemm_fp16<128,128,4,2,2><<<dim3(DIN/128, NT/128), 256, SMEM_128>>>(
        db16, 64, dtph, DTR, nullptr, dt16, nullptr, DIN, 2,
        dt_proj_b, nullptr, nullptr, nullptr, nullptr);

    // 6) selective scan (R12) -> y (fp16)
    scan_kernel<<<dim3(DIN / SD, NB), 64>>>(dt16, bq, cq, uz16, A_log, Dp, y16);

    // 7) og = fp16(y @ out_proj_w^T) scattered by order == o1[inv]
    gemm_fp16<64,128,2,4,3><<<dim3(CC/128, NT/64), 256, SMEM_64N128>>>(
        y16, DIN, oph, DIN, nullptr, og16, order, CC, 0,
        nullptr, nullptr, nullptr, nullptr, nullptr);

    // 8) out = relu(BN(og @ W_out^T) + x)
    gemm_fp16<64,128,2,4,3><<<dim3(CC/128, NT/64), 256, SMEM_64N128>>>(
        og16, CC, Woh, CC, out, nullptr, nullptr, CC, 3,
        bn_o_g, bn_o_b, bn_o_m, bn_o_v, x);
}

// round 16
// speedup vs baseline: 1.1125x; 1.0703x over previous
#include <cuda_runtime.h>
#include <cuda_fp16.h>
#include <math.h>
#include <stdint.h>

// Problem constants
#define NB 4
#define LL 2048
#define CC 512
#define DIN 1024
#define DS 16
#define DCONV 4
#define DTR 32
#define NT (NB * LL)   // 8192 rows
#define EPSBN 1e-5f

// ---------------- scratch (device globals; no allocation allowed) -------------
__device__ __align__(256) __half  g_x16 [NT * CC];
__device__ __align__(256) __half  g_hg16[NT * CC];
__device__ __align__(256) __half  g_xz16[NT * 2 * DIN];
__device__ __align__(256) __half  g_xc16[NT * DIN];
__device__ __align__(256) __half  g_db16[NT * 64];
__device__ __align__(256) __half  g_dt16[NT * DIN];
__device__ __align__(256) __half2 g_uz16[NT * DIN];   // {silu(u), silu(z)}
__device__ __align__(256) float2  g_bq  [NT * 8];     // {B_2sl, B_2sl+1}
__device__ __align__(256) float2  g_cq  [NT * 8];     // {C_2sl, C_2sl+1}
__device__ __align__(256) __half  g_y16 [NT * DIN];
// fp16 weights
__device__ __align__(256) __half g_Win_h[CC * CC];
__device__ __align__(256) __half g_ip_h [2 * DIN * CC];
__device__ __align__(256) __half g_xp_h [64 * DIN];
__device__ __align__(256) __half g_dtp_h[DIN * DTR];
__device__ __align__(256) __half g_Wo_h [CC * CC];
__device__ __align__(256) __half g_opt  [DIN * CC];   // op^T (1024 x 512)
__device__ __align__(256) __half g_Wcomb[CC * DIN];   // W_out @ op (512 x 1024)

// ============================ PTX helpers =====================================
__device__ __forceinline__ uint32_t smem_u32(const void* p) {
    uint32_t a;
    asm("{ .reg .u64 t; cvta.to.shared.u64 t, %1; cvt.u32.u64 %0, t; }"
        : "=r"(a) : "l"(p));
    return a;
}
__device__ __forceinline__ void cpa16(uint32_t d, const void* s) {
    asm volatile("cp.async.cg.shared.global [%0], [%1], 16;" :: "r"(d), "l"(s));
}
#define CP_COMMIT asm volatile("cp.async.commit_group;" ::: "memory")
#define CP_WAIT1  asm volatile("cp.async.wait_group 1;"  ::: "memory")
#define CP_WAIT2  asm volatile("cp.async.wait_group 2;"  ::: "memory")

__device__ __forceinline__ void ldsm4(uint32_t* r, uint32_t a) {
    asm volatile("ldmatrix.sync.aligned.m8n8.x4.shared.b16 {%0,%1,%2,%3}, [%4];"
        : "=r"(r[0]), "=r"(r[1]), "=r"(r[2]), "=r"(r[3]) : "r"(a));
}
__device__ __forceinline__ void mma16816(float* c, const uint32_t* a, const uint32_t* b) {
    asm volatile(
        "mma.sync.aligned.m16n8k16.row.col.f32.f16.f16.f32 "
        "{%0,%1,%2,%3}, {%4,%5,%6,%7}, {%8,%9}, {%0,%1,%2,%3};"
        : "+f"(c[0]), "+f"(c[1]), "+f"(c[2]), "+f"(c[3])
        : "r"(a[0]), "r"(a[1]), "r"(a[2]), "r"(a[3]), "r"(b[0]), "r"(b[1]));
}

// ====================== single-term fp16 HMMA GEMM ============================
// C[M,N] = epi( A[M,K] @ W[N,K]^T ). CTA MT x NTILE, 256 thr, 8 warps
// (WMW x WNW), 4-stage cp.async pipeline, MINB CTAs/SM.
// epi: 0 none | 1 BN+relu | 2 softplus | 3 BN+addsrc+relu (scatter)
//      4 split: n<32 -> outH, n in [32,48) -> bq (=p0), [48,64) -> cq (=p1)
template <int MT, int NTILE>
__device__ __forceinline__ void load_stage(
    uint32_t base, int tid, int m0, int n0, int lda, int K, int c,
    const __half* A, const __half* W)
{
    const int k0 = c * 32;
    #pragma unroll
    for (int e = 0; e < MT * 4 / 256; e++) {
        int t = tid + e * 256;
        int r = t >> 2, g = t & 3;
        cpa16(base + r * 80 + g * 16, A + (size_t)(m0 + r) * lda + k0 + g * 8);
    }
    uint32_t dw = base + (uint32_t)MT * 80;
    #pragma unroll
    for (int e = 0; e < NTILE * 4 / 256; e++) {
        int t = tid + e * 256;
        int r = t >> 2, g = t & 3;
        cpa16(dw + r * 80 + g * 16, W + (size_t)(n0 + r) * K + k0 + g * 8);
    }
}

template <int MT, int NTILE, int WMW, int WNW, int MINB>
__global__ void __launch_bounds__(256, MINB) gemm_fp16(
    const __half* __restrict__ A, int lda,
    const __half* __restrict__ W, int K,
    float* __restrict__ outF, __half* __restrict__ outH,
    const int* __restrict__ scat, int Ntot, int epi,
    const float* __restrict__ p0, const float* __restrict__ p1,
    const float* __restrict__ p2, const float* __restrict__ p3,
    const float* __restrict__ addsrc)
{
    constexpr int WTM = MT / WMW;
    constexpr int WTN = NTILE / WNW;
    constexpr int MTFR = WTM / 16;
    constexpr int NT8 = WTN / 8;
    constexpr int STAGE = (MT + NTILE) * 80;

    extern __shared__ __align__(128) char smraw[];
    const uint32_t sb = smem_u32(smraw);

    const int tid = threadIdx.x;
    const int lane = tid & 31, warp = tid >> 5;
    const int wm = warp % WMW, wn = warp / WMW;
    const int m0 = blockIdx.y * MT;
    const int n0 = blockIdx.x * NTILE;

    float acc[MTFR][NT8][4] = {};

    const int nch = K >> 5;
    #pragma unroll
    for (int s = 0; s < 3; s++) {
        if (s < nch)
            load_stage<MT, NTILE>(sb + s * STAGE, tid, m0, n0, lda, K, s, A, W);
        CP_COMMIT;
    }

    const int lr = lane & 15;
    const int lc = (lane >> 4) << 3;

    for (int c = 0; c < nch; c++) {
        CP_WAIT2;
        __syncthreads();
        {
            int cn = c + 3;
            if (cn < nch)
                load_stage<MT, NTILE>(sb + (cn & 3) * STAGE, tid, m0, n0, lda, K, cn, A, W);
            CP_COMMIT;
        }
        const uint32_t cur = sb + (uint32_t)(c & 3) * STAGE;
        #pragma unroll
        for (int kk = 0; kk < 32; kk += 16) {
            uint32_t af[MTFR][4];
            #pragma unroll
            for (int mt = 0; mt < MTFR; mt++)
                ldsm4(af[mt], cur + (uint32_t)((wm * WTM + mt * 16 + lr) * 80 + (kk + lc) * 2));
            uint32_t wf[NT8][2];
            #pragma unroll
            for (int p = 0; p < NT8 / 2; p++) {
                uint32_t a = cur + (uint32_t)((MT + wn * WTN + p * 16 + lr) * 80 + (kk + lc) * 2);
                uint32_t r4[4];
                ldsm4(r4, a);
                wf[2*p][0] = r4[0]; wf[2*p][1] = r4[2];
                wf[2*p+1][0] = r4[1]; wf[2*p+1][1] = r4[3];
            }
            #pragma unroll
            for (int mt = 0; mt < MTFR; mt++)
                #pragma unroll
                for (int nt = 0; nt < NT8; nt++)
                    mma16816(acc[mt][nt], af[mt], wf[nt]);
        }
    }

    const int g = lane >> 2, tg = lane & 3;
    #pragma unroll
    for (int mt = 0; mt < MTFR; mt++)
        #pragma unroll
        for (int nt = 0; nt < NT8; nt++)
            #pragma unroll
            for (int rr = 0; rr < 2; rr++) {
                int m = m0 + wm * WTM + mt * 16 + g + rr * 8;
                int n = n0 + wn * WTN + nt * 8 + tg * 2;
                int mo = scat ? scat[m] : m;
                float v0 = acc[mt][nt][rr * 2 + 0];
                float v1 = acc[mt][nt][rr * 2 + 1];
                if (epi == 1) {
                    v0 = fmaxf((v0 - p2[n])   * rsqrtf(p3[n]   + EPSBN) * p0[n]   + p1[n],   0.f);
                    v1 = fmaxf((v1 - p2[n+1]) * rsqrtf(p3[n+1] + EPSBN) * p0[n+1] + p1[n+1], 0.f);
                } else if (epi == 2) {
                    v0 += p0[n];   v0 = (v0 > 20.f) ? v0 : __logf(1.f + __expf(v0));
                    v1 += p0[n+1]; v1 = (v1 > 20.f) ? v1 : __logf(1.f + __expf(v1));
                } else if (epi == 3) {
                    v0 = (v0 - p2[n])   * rsqrtf(p3[n]   + EPSBN) * p0[n]   + p1[n];
                    v1 = (v1 - p2[n+1]) * rsqrtf(p3[n+1] + EPSBN) * p0[n+1] + p1[n+1];
                    v0 = fmaxf(v0 + addsrc[(size_t)mo * Ntot + n], 0.f);
                    v1 = fmaxf(v1 + addsrc[(size_t)mo * Ntot + n + 1], 0.f);
                }
                const size_t ob = (size_t)mo * Ntot + n;
                if (epi == 4) {
                    if (n < DTR)
                        *(__half2*)&outH[ob] =
                            __halves2half2(__float2half_rn(v0), __float2half_rn(v1));
                    else if (n < DTR + DS)
                        ((float2*)p0)[(size_t)mo * 8 + ((n - DTR) >> 1)] =
                            make_float2(v0, v1);
                    else
                        ((float2*)p1)[(size_t)mo * 8 + ((n - DTR - DS) >> 1)] =
                            make_float2(v0, v1);
                } else {
                    if (outF) *(float2*)&outF[ob] = make_float2(v0, v1);
                    if (outH)
                        *(__half2*)&outH[ob] =
                            __halves2half2(__float2half_rn(v0), __float2half_rn(v1));
                }
            }
}

// ====================== prep (x + weights -> fp16), one launch ================
__global__ void __launch_bounds__(256) prep_all_kernel(
    const float* __restrict__ x,
    const float* __restrict__ Win, const float* __restrict__ ip,
    const float* __restrict__ xp,  const float* __restrict__ dtp,
    const float* __restrict__ Wo,
    __half* __restrict__ dx,
    __half* __restrict__ dWin, __half* __restrict__ dip,
    __half* __restrict__ dxp,  __half* __restrict__ ddtp,
    __half* __restrict__ dWo)
{
    const int sx = NT * CC, s0 = CC * CC, s1 = 2 * DIN * CC, s2 = 64 * DIN,
              s3 = DIN * DTR;
    int i = blockIdx.x * blockDim.x + threadIdx.x;
    if (i < sx) { dx[i]   = __float2half_rn(x[i]);   return; } i -= sx;
    if (i < s0) { dWin[i] = __float2half_rn(Win[i]); return; } i -= s0;
    if (i < s1) { dip[i]  = __float2half_rn(ip[i]);  return; } i -= s1;
    if (i < s2) { dxp[i]  = __float2half_rn(xp[i]);  return; } i -= s2;
    if (i < s3) { ddtp[i] = __float2half_rn(dtp[i]); return; } i -= s3;
    dWo[i] = __float2half_rn(Wo[i]);
}

// op (CC x DIN fp32) -> op^T (DIN x CC fp16), 32x32 SMEM tiles
__global__ void __launch_bounds__(256) transpose_op_kernel(
    const float* __restrict__ op, __half* __restrict__ opt)
{
    __shared__ __half tile[32][33];
    const int bx = blockIdx.x * 32;   // DIN dimension
    const int by = blockIdx.y * 32;   // CC dimension
    const int tx = threadIdx.x & 31, ty = threadIdx.x >> 5;
    #pragma unroll
    for (int i = ty; i < 32; i += 8)
        tile[i][tx] = __float2half_rn(op[(size_t)(by + i) * DIN + bx + tx]);
    __syncthreads();
    #pragma unroll
    for (int i = ty; i < 32; i += 8)
        opt[(size_t)(bx + i) * CC + by + tx] = tile[tx][i];
}

// ---------- depthwise causal conv: register-blocked 8 rows x 2 channels -------
__global__ void __launch_bounds__(256) conv_silu_kernel(
    const __half2* __restrict__ xz2,
    const float* __restrict__ cw, const float* __restrict__ cb,
    __half2* __restrict__ xch2, __half2* __restrict__ uz)
{
    int g   = blockIdx.x * blockDim.x + threadIdx.x;  // over (NT/8)*(DIN/2)
    int dp  = g & (DIN / 2 - 1);
    int rg  = g >> 9;
    int row0 = rg * 8;
    int l0   = row0 & (LL - 1);
    int d    = dp * 2;

    const float bx  = cb[d],     by  = cb[d + 1];
    const float c0x = cw[d*4+0], c1x = cw[d*4+1], c2x = cw[d*4+2], c3x = cw[d*4+3];
    const float c0y = cw[d*4+4], c1y = cw[d*4+5], c2y = cw[d*4+6], c3y = cw[d*4+7];

    float2 w[11];
    #pragma unroll
    for (int j = 0; j < 11; j++) {
        int l = l0 - 3 + j;
        w[j] = (l >= 0)
             ? __half22float2(xz2[(long)(row0 - 3 + j) * DIN + dp])
             : make_float2(0.f, 0.f);
    }

    #pragma unroll
    for (int i = 0; i < 8; i++) {
        const long row = row0 + i;
        float ax = bx, ay = by;
        ax = fmaf(c0x, w[i].x,   ax); ay = fmaf(c0y, w[i].y,   ay);
        ax = fmaf(c1x, w[i+1].x, ax); ay = fmaf(c1y, w[i+1].y, ay);
        ax = fmaf(c2x, w[i+2].x, ax); ay = fmaf(c2y, w[i+2].y, ay);
        ax = fmaf(c3x, w[i+3].x, ax); ay = fmaf(c3y, w[i+3].y, ay);

        float ux = __fdividef(ax, 1.f + __expf(-ax));
        float uy = __fdividef(ay, 1.f + __expf(-ay));
        float2 zf = __half22float2(xz2[row * DIN + DIN / 2 + dp]);
        float gx = __fdividef(zf.x, 1.f + __expf(-zf.x));
        float gy = __fdividef(zf.y, 1.f + __expf(-zf.y));

        xch2[row * (DIN / 2) + dp] =
            __halves2half2(__float2half_rn(ux), __float2half_rn(uy));
        __half2 a = __halves2half2(__float2half_rn(ux), __float2half_rn(gx));
        __half2 b = __halves2half2(__float2half_rn(uy), __float2half_rn(gy));
        uint2 pk = make_uint2(*(uint32_t*)&a, *(uint32_t*)&b);
        *(uint2*)&uz[row * DIN + d] = pk;
    }
}

// ---------------- selective scan: 2 states/lane, 4 d/warp (R12 version) -------
#define SD 8
#define ST 64

__global__ void __launch_bounds__(64) scan_kernel(
    const __half* __restrict__ dtg, const float2* __restrict__ bqg,
    const float2* __restrict__ cqg, const __half2* __restrict__ uzg,
    const float* __restrict__ A_log, const float* __restrict__ Dp,
    __half* __restrict__ yh)
{
    __shared__ __align__(16) __half  s_dt[3][ST][SD];
    __shared__ __align__(16) __half2 s_uz[3][ST][SD];
    __shared__ __align__(16) float2  s_b[3][ST][8];
    __shared__ __align__(16) float2  s_c[3][ST][8];
    __shared__ __align__(16) __half  s_y[2][ST][SD];

    const int tid  = threadIdx.x;
    const int warp = tid >> 5, lane = tid & 31;
    const int sl   = lane & 7, dl = lane >> 3;
    const int dg   = warp * 4 + dl;
    const int d0   = blockIdx.x * SD;
    const int d    = d0 + dg;
    const long rbase = (long)blockIdx.y * LL;

    const float A0 = -expf(A_log[d * DS + 2 * sl]);
    const float A1 = -expf(A_log[d * DS + 2 * sl + 1]);
    const float Dd = Dp[d];

    auto stage_load = [&](int st, int buf) {
        const long row0 = rbase + (long)st * ST;
        for (int j = tid; j < 704; j += 64) {
            if (j < 64) {
                cpa16(smem_u32(&s_dt[buf][j][0]), dtg + (row0 + j) * DIN + d0);
            } else if (j < 192) {
                int u = j - 64, r = u >> 1, q = u & 1;
                cpa16(smem_u32(&s_uz[buf][r][q * 4]),
                      uzg + (row0 + r) * DIN + d0 + q * 4);
            } else if (j < 448) {
                int v = j - 192, r = v >> 2, q = v & 3;
                cpa16(smem_u32(&s_b[buf][r][q * 2]), bqg + (row0 + r) * 8 + q * 2);
            } else {
                int v = j - 448, r = v >> 2, q = v & 3;
                cpa16(smem_u32(&s_c[buf][r][q * 2]), cqg + (row0 + r) * 8 + q * 2);
            }
        }
    };
    auto flush_y = [&](int st, int yb) {
        const long row0 = rbase + (long)st * ST;
        #pragma unroll
        for (int j0 = 0; j0 < 256; j0 += 64) {
            int j = tid + j0;
            int r = j >> 2, w = j & 3;
            uint32_t val = ((const uint32_t*)&s_y[yb][r][0])[w];
            *(uint32_t*)(yh + (row0 + r) * DIN + d0 + w * 2) = val;
        }
    };

    stage_load(0, 0); CP_COMMIT;
    stage_load(1, 1); CP_COMMIT;

    float h0 = 0.f, h1 = 0.f;
    const int NST = LL / ST;   // 32
    for (int ts = 0; ts < NST; ts++) {
        CP_WAIT1;
        __syncthreads();
        if (ts > 0) flush_y(ts - 1, (ts - 1) & 1);
        const int buf = ts % 3;
        if (ts + 2 < NST) stage_load(ts + 2, (ts + 2) % 3);
        CP_COMMIT;

        const int yb = ts & 1;
        #pragma unroll
        for (int t8 = 0; t8 < ST; t8 += 8) {
            float p8[8], g8[8];
            #pragma unroll
            for (int i = 0; i < 8; i++) {
                const int t = t8 + i;
                float  dtv = __half2float(s_dt[buf][t][dg]);
                float2 uzv = __half22float2(s_uz[buf][t][dg]);
                float2 bv  = s_b[buf][t][sl];
                float2 cv  = s_c[buf][t][sl];
                float dA0 = __expf(dtv * A0);
                float dA1 = __expf(dtv * A1);
                float cx = dtv * uzv.x;
                h0 = fmaf(dA0, h0, cx * bv.x);
                h1 = fmaf(dA1, h1, cx * bv.y);
                float p = fmaf(h1, cv.y, h0 * cv.x);
                if (sl == 0) p = fmaf(uzv.x, Dd, p);
                p8[i] = p;
                g8[i] = uzv.y;
            }
            #pragma unroll
            for (int i = 0; i < 8; i += 2) {
                __half2 pp = __halves2half2(__float2half_rn(p8[i]),
                                            __float2half_rn(p8[i+1]));
                uint32_t u = *(uint32_t*)&pp;
                #pragma unroll
                for (int k = 4; k >= 1; k >>= 1) {
                    uint32_t v = __shfl_xor_sync(0xffffffffu, u, k, 8);
                    __half2 va = *(__half2*)&u, vb = *(__half2*)&v;
                    va = __hadd2(va, vb);
                    u = *(uint32_t*)&va;
                }
                if (sl == 0) {
                    __half2 r = *(__half2*)&u;
                    s_y[yb][t8 + i][dg] =
                        __hmul(__low2half(r),  __float2half_rn(g8[i]));
                    s_y[yb][t8 + i + 1][dg] =
                        __hmul(__high2half(r), __float2half_rn(g8[i+1]));
                }
            }
        }
    }
    __syncthreads();
    flush_y(NST - 1, (NST - 1) & 1);
}

// ---------------- launch -------------------------------------------------------
extern "C" void kernel_launch(void* const* d_in, const int* in_sizes, int n_in,
                              void* d_out, int out_size)
{
    const float* x          = (const float*)d_in[1];
    const int*   order      = (const int*)  d_in[3];
    const float* W_in       = (const float*)d_in[5];
    const float* bn_in_g    = (const float*)d_in[6];
    const float* bn_in_b    = (const float*)d_in[7];
    const float* bn_in_m    = (const float*)d_in[8];
    const float* bn_in_v    = (const float*)d_in[9];
    const float* in_proj_w  = (const float*)d_in[10];
    const float* conv_w     = (const float*)d_in[11];
    const float* conv_b     = (const float*)d_in[12];
    const float* x_proj_w   = (const float*)d_in[13];
    const float* dt_proj_w  = (const float*)d_in[14];
    const float* dt_proj_b  = (const float*)d_in[15];
    const float* A_log      = (const float*)d_in[16];
    const float* Dp         = (const float*)d_in[17];
    const float* out_proj_w = (const float*)d_in[18];
    const float* W_out      = (const float*)d_in[19];
    const float* bn_o_g     = (const float*)d_in[20];
    const float* bn_o_b     = (const float*)d_in[21];
    const float* bn_o_m     = (const float*)d_in[22];
    const float* bn_o_v     = (const float*)d_in[23];
    const int*   inv        = (const int*)  d_in[4];
    float* out = (float*)d_out;

    __half *x16, *hg16, *xz16, *xc16, *db16, *dt16, *y16;
    __half2 *uz16;
    float2 *bq, *cq;
    __half *Winh, *iph, *xph, *dtph, *Woh, *opt, *Wcomb;
    cudaGetSymbolAddress((void**)&x16,  g_x16);
    cudaGetSymbolAddress((void**)&hg16, g_hg16);
    cudaGetSymbolAddress((void**)&xz16, g_xz16);
    cudaGetSymbolAddress((void**)&xc16, g_xc16);
    cudaGetSymbolAddress((void**)&db16, g_db16);
    cudaGetSymbolAddress((void**)&dt16, g_dt16);
    cudaGetSymbolAddress((void**)&uz16, g_uz16);
    cudaGetSymbolAddress((void**)&bq,   g_bq);
    cudaGetSymbolAddress((void**)&cq,   g_cq);
    cudaGetSymbolAddress((void**)&y16,  g_y16);
    cudaGetSymbolAddress((void**)&Winh, g_Win_h);
    cudaGetSymbolAddress((void**)&iph,  g_ip_h);
    cudaGetSymbolAddress((void**)&xph,  g_xp_h);
    cudaGetSymbolAddress((void**)&dtph, g_dtp_h);
    cudaGetSymbolAddress((void**)&Woh,  g_Wo_h);
    cudaGetSymbolAddress((void**)&opt,  g_opt);
    cudaGetSymbolAddress((void**)&Wcomb,g_Wcomb);

    const int SMEM_128 = 4 * (128 + 128) * 80;   // 81920
    const int SMEM_64  = 4 * (64 + 64) * 80;     // 40960
    cudaFuncSetAttribute((const void*)gemm_fp16<128,128,4,2,2>,
                         cudaFuncAttributeMaxDynamicSharedMemorySize, SMEM_128);
    cudaFuncSetAttribute((const void*)gemm_fp16<64,64,2,4,2>,
                         cudaFuncAttributeMaxDynamicSharedMemorySize, SMEM_64);

    // prep: x + weights -> fp16; op^T (fp16)
    {
        const int total = NT*CC + CC*CC + 2*DIN*CC + 64*DIN + DIN*DTR + CC*CC;
        prep_all_kernel<<<(total + 255) / 256, 256>>>(
            x, W_in, in_proj_w, x_proj_w, dt_proj_w, W_out,
            x16, Winh, iph, xph, dtph, Woh);
    }
    transpose_op_kernel<<<dim3(DIN / 32, CC / 32), 256>>>(out_proj_w, opt);

    // Wcomb = W_out @ op   (512 x 1024, fp16)
    gemm_fp16<64,64,2,4,2><<<dim3(DIN/64, CC/64), 256, SMEM_64>>>(
        Woh, CC, opt, CC, nullptr, Wcomb, nullptr, DIN, 0,
        nullptr, nullptr, nullptr, nullptr, nullptr);

    // 1) hg = fp16(relu(BN(x @ W_in^T))) scattered by inv  ==  h[order]
    gemm_fp16<128,128,4,2,2><<<dim3(CC/128, NT/128), 256, SMEM_128>>>(
        x16, CC, Winh, CC, nullptr, hg16, inv, CC, 1,
        bn_in_g, bn_in_b, bn_in_m, bn_in_v, nullptr);

    // 2) xz = hg @ in_proj_w^T
    gemm_fp16<128,128,4,2,2><<<dim3(2*DIN/128, NT/128), 256, SMEM_128>>>(
        hg16, CC, iph, CC, nullptr, xz16, nullptr, 2*DIN, 0,
        nullptr, nullptr, nullptr, nullptr, nullptr);

    // 3) xc16 + packed {u, gate}
    conv_silu_kernel<<<(NT / 8) * (DIN / 2) / 256, 256>>>(
        (const __half2*)xz16, conv_w, conv_b, (__half2*)xc16, uz16);

    // 4) db16 (dt_low cols) + bq/cq direct (epi 4)
    gemm_fp16<64,64,2,4,2><<<dim3(1, NT/64), 256, SMEM_64>>>(
        xc16, DIN, xph, DIN, nullptr, db16, nullptr, 64, 4,
        (const float*)bq, (const float*)cq, nullptr, nullptr, nullptr);

    // 5) dt16 = fp16(softplus(dt_low @ dt_proj_w^T + b)), K=32 (lda=64)
    gemm_fp16<128,128,4,2,2><<<dim3(DIN/128, NT/128), 256, SMEM_128>>>(
        db16, 64, dtph, DTR, nullptr, dt16, nullptr, DIN, 2,
        dt_proj_b, nullptr, nullptr, nullptr, nullptr);

    // 6) selective scan (R12) -> y (fp16)
    scan_kernel<<<dim3(DIN / SD, NB), 64>>>(dt16, bq, cq, uz16, A_log, Dp, y16);

    // 7) out[order[m]] = relu(BN(y[m] @ Wcomb^T) + x[order[m]])  (g7+g8 fused)
    gemm_fp16<128,128,4,2,2><<<dim3(CC/128, NT/128), 256, SMEM_128>>>(
        y16, DIN, Wcomb, DIN, out, nullptr, order, CC, 3,
        bn_o_g, bn_o_b, bn_o_m, bn_o_v, x);
}